// round 16
// baseline (speedup 1.0000x reference)
#include <cuda_runtime.h>

#define TPB 128
#define ROW 63            // 21 joints * 3
#define WROW (32*ROW)     // 2016 floats per warp region
#define WV4 (WROW/4)      // 504 float4 per warp region
#define NBS 11            // bone lengths kept in smem (stride 11, odd -> conflict-free)
#define NSWEEP 3          // Jacobi sweeps (2 measured FAIL at 2.8e-3; 3 gives 1.2e-5)

// fast sqrt via MUFU.RSQ (no Newton tail); eps keeps 0 -> 0
__device__ __forceinline__ float fsqrt_fast(float x) {
    return x * rsqrtf(x + 1e-30f);
}

__global__ void __launch_bounds__(TPB, 6)
kin_kernel(const float* __restrict__ joints,
           const float* __restrict__ tempJ,
           float* __restrict__ out, int n)
{
    __shared__ __align__(16) float sm[TPB * ROW];   // 32256 B, reused 3x
    __shared__ float sblen[TPB * NBS];              // 5632 B
    const int tid  = threadIdx.x;
    const int lane = tid & 31;
    const int wid  = tid >> 5;
    const long long total = (long long)n * ROW;
    // per-warp global base: this warp's 32 samples
    const long long wg = ((long long)blockIdx.x * TPB + wid * 32) * ROW;
    const bool wfull = (wg + WROW) <= total;
    const bool active = ((long long)blockIdx.x * TPB + tid) < n;
    const int wsm = wid * WROW;          // warp's smem region
    const int base = tid * ROW;          // == wsm + lane*ROW
    const int bbase = tid * NBS;

    const int PALM5[5] = {1, 4, 7, 10, 13};
    const int CH[15] = {2,3,17, 5,6,18, 8,9,20, 11,12,19, 14,15,16};
    const int PA[15] = {1,2,3, 4,5,6, 7,8,9, 10,11,12, 13,14,15};

    // ====== prefetch this warp's joints region into L2 (consumed in phase 2) ======
    if (wfull) {
        const char* bp = (const char*)(joints + wg);   // 8064 B = 63 x 128B lines
        asm volatile("prefetch.global.L2 [%0];" :: "l"(bp + lane * 128));
        if (lane < 31)
            asm volatile("prefetch.global.L2 [%0];" :: "l"(bp + (32 + lane) * 128));
    }

    // ================= stage tempJ (coalesced float4, own warp region) =========
    if (wfull) {
        #pragma unroll
        for (int i = 0; i < 16; ++i) {
            int q = i * 32 + lane;
            if (q < WV4)
                reinterpret_cast<float4*>(sm + wsm)[q] =
                    reinterpret_cast<const float4*>(tempJ + wg)[q];
        }
    } else {
        for (int q = lane; q < WROW; q += 32) {
            long long g = wg + q;
            if (g < total) sm[wsm + q] = tempJ[g];
        }
    }
    __syncwarp();

    // extract from template: centered palm points (regs) + bone lengths
    // bones 0..10 -> smem (stride 11); bones 11..14 -> registers
    float sp[5][3];
    float blr11 = 0.f, blr12 = 0.f, blr13 = 0.f, blr14 = 0.f;
    if (active) {
        const float t0x = sm[base + 0], t0y = sm[base + 1], t0z = sm[base + 2];
        #pragma unroll
        for (int p = 0; p < 5; ++p) {
            sp[p][0] = sm[base + 3 * PALM5[p] + 0] - t0x;
            sp[p][1] = sm[base + 3 * PALM5[p] + 1] - t0y;
            sp[p][2] = sm[base + 3 * PALM5[p] + 2] - t0z;
        }
        #pragma unroll
        for (int i = 0; i < 15; ++i) {
            float bx = sm[base + 3*CH[i] + 0] - sm[base + 3*PA[i] + 0];
            float by = sm[base + 3*CH[i] + 1] - sm[base + 3*PA[i] + 1];
            float bz = sm[base + 3*CH[i] + 2] - sm[base + 3*PA[i] + 2];
            float bl = fsqrt_fast(bx*bx + by*by + bz*bz);
            if (i < NBS)       sblen[bbase + i] = bl;
            else if (i == 11)  blr11 = bl;
            else if (i == 12)  blr12 = bl;
            else if (i == 13)  blr13 = bl;
            else               blr14 = bl;
        }
    }
    __syncwarp();

    // ================= stage joints (overwrite own warp region) ================
    if (wfull) {
        #pragma unroll
        for (int i = 0; i < 16; ++i) {
            int q = i * 32 + lane;
            if (q < WV4)
                reinterpret_cast<float4*>(sm + wsm)[q] =
                    reinterpret_cast<const float4*>(joints + wg)[q];
        }
    } else {
        for (int q = lane; q < WROW; q += 32) {
            long long g = wg + q;
            if (g < total) sm[wsm + q] = joints[g];
        }
    }
    __syncwarp();

    if (active) {
        const float wx = sm[base + 0], wy = sm[base + 1], wz = sm[base + 2];

        // ---- H = sum_palm src ⊗ dst ----
        float H[3][3] = {{0,0,0},{0,0,0},{0,0,0}};
        #pragma unroll
        for (int p = 0; p < 5; ++p) {
            float jx = sm[base + 3 * PALM5[p] + 0] - wx;
            float jy = sm[base + 3 * PALM5[p] + 1] - wy;
            float jz = sm[base + 3 * PALM5[p] + 2] - wz;
            H[0][0] += sp[p][0]*jx; H[0][1] += sp[p][0]*jy; H[0][2] += sp[p][0]*jz;
            H[1][0] += sp[p][1]*jx; H[1][1] += sp[p][1]*jy; H[1][2] += sp[p][1]*jz;
            H[2][0] += sp[p][2]*jx; H[2][1] += sp[p][2]*jy; H[2][2] += sp[p][2]*jz;
        }

        // ---- A = H^T H ; NSWEEP-sweep division-free cyclic Jacobi ----
        float A[3][3];
        #pragma unroll
        for (int a = 0; a < 3; ++a)
            #pragma unroll
            for (int b = 0; b < 3; ++b)
                A[a][b] = H[0][a]*H[0][b] + H[1][a]*H[1][b] + H[2][a]*H[2][b];

        float V[3][3] = {{1,0,0},{0,1,0},{0,0,1}};
        #pragma unroll
        for (int sweep = 0; sweep < NSWEEP; ++sweep) {
            #pragma unroll
            for (int pair = 0; pair < 3; ++pair) {
                const int p = (pair == 2) ? 1 : 0;
                const int q = (pair == 0) ? 1 : 2;
                const int r = 3 - p - q;
                float apq = A[p][q];
                float x = 0.5f * (A[q][q] - A[p][p]);
                // inner rotation annihilating apq: tan(2θ) = apq/x, |θ| <= 45°
                float rinv = rsqrtf(x*x + apq*apq + 1e-36f);
                float co = (fabsf(x) + 1e-18f) * rinv;        // cos2θ (>=0)
                float si = apq * copysignf(1.0f, x) * rinv;   // sin2θ = apq·sign(x)/r
                float h  = 0.5f + 0.5f * co;                  // c²
                float cinv = rsqrtf(h);                       // 1/c
                float c = h * cinv;
                float s = 0.5f * si * cinv;
                float t = s * cinv;                           // tanθ
                A[p][p] -= t * apq;
                A[q][q] += t * apq;
                // after the very last rotation only the diagonal is consumed
                if (!(sweep == NSWEEP - 1 && pair == 2)) {
                    A[p][q] = 0.f; A[q][p] = 0.f;
                    float arp = A[r][p], arq = A[r][q];
                    A[r][p] = c * arp - s * arq; A[p][r] = A[r][p];
                    A[r][q] = s * arp + c * arq; A[q][r] = A[r][q];
                }
                #pragma unroll
                for (int k = 0; k < 3; ++k) {
                    float vp = V[k][p], vq = V[k][q];
                    V[k][p] = c * vp - s * vq;
                    V[k][q] = s * vp + c * vq;
                }
            }
        }

        // sort eigenvalues (descending) -> v1, v2; v3 = v1 x v2
        float e0 = A[0][0], e1 = A[1][1], e2 = A[2][2];
        int i0 = 0; float em = e0;
        if (e1 > em) { i0 = 1; em = e1; }
        if (e2 > em) { i0 = 2; em = e2; }
        const int a1 = (i0 + 1) % 3, b1 = (i0 + 2) % 3;
        float ea = (a1 == 0) ? e0 : (a1 == 1) ? e1 : e2;
        float eb = (b1 == 0) ? e0 : (b1 == 1) ? e1 : e2;
        const int i1 = (ea >= eb) ? a1 : b1;

        float v1[3], v2[3], v3[3];
        #pragma unroll
        for (int k = 0; k < 3; ++k) {
            v1[k] = (i0 == 0) ? V[k][0] : (i0 == 1) ? V[k][1] : V[k][2];
            v2[k] = (i1 == 0) ? V[k][0] : (i1 == 1) ? V[k][1] : V[k][2];
        }
        v3[0] = v1[1]*v2[2] - v1[2]*v2[1];
        v3[1] = v1[2]*v2[0] - v1[0]*v2[2];
        v3[2] = v1[0]*v2[1] - v1[1]*v2[0];

        // u1 = norm(H v1); u2 = norm(GS(H v2)); u3 = u1 x u2
        float u1[3], u2[3], u3[3];
        #pragma unroll
        for (int k = 0; k < 3; ++k)
            u1[k] = H[k][0]*v1[0] + H[k][1]*v1[1] + H[k][2]*v1[2];
        {
            float inv = rsqrtf(u1[0]*u1[0] + u1[1]*u1[1] + u1[2]*u1[2] + 1e-30f);
            u1[0] *= inv; u1[1] *= inv; u1[2] *= inv;
        }
        #pragma unroll
        for (int k = 0; k < 3; ++k)
            u2[k] = H[k][0]*v2[0] + H[k][1]*v2[1] + H[k][2]*v2[2];
        {
            float pr = u1[0]*u2[0] + u1[1]*u2[1] + u1[2]*u2[2];
            u2[0] -= pr * u1[0]; u2[1] -= pr * u1[1]; u2[2] -= pr * u1[2];
            float inv = rsqrtf(u2[0]*u2[0] + u2[1]*u2[1] + u2[2]*u2[2] + 1e-30f);
            u2[0] *= inv; u2[1] *= inv; u2[2] *= inv;
        }
        u3[0] = u1[1]*u2[2] - u1[2]*u2[1];
        u3[1] = u1[2]*u2[0] - u1[0]*u2[2];
        u3[2] = u1[0]*u2[1] - u1[1]*u2[0];

        // R = v1 u1^T + v2 u2^T + v3 u3^T
        float R[3][3];
        #pragma unroll
        for (int a = 0; a < 3; ++a)
            #pragma unroll
            for (int b = 0; b < 3; ++b)
                R[a][b] = v1[a]*u1[b] + v2[a]*u2[b] + v3[a]*u3[b];

        // ---- rotate template palm points (absolute coords), write in place ----
        #pragma unroll
        for (int p = 0; p < 5; ++p) {
            float tx = R[0][0]*sp[p][0] + R[0][1]*sp[p][1] + R[0][2]*sp[p][2] + wx;
            float ty = R[1][0]*sp[p][0] + R[1][1]*sp[p][1] + R[1][2]*sp[p][2] + wy;
            float tz = R[2][0]*sp[p][0] + R[2][1]*sp[p][1] + R[2][2]*sp[p][2] + wz;
            sm[base + 3*PALM5[p] + 0] = tx;
            sm[base + 3*PALM5[p] + 1] = ty;
            sm[base + 3*PALM5[p] + 2] = tz;
        }
        // wrist slot already holds w

        // ---- kinematic chain, finger-major, absolute coords, direct-M clamp ----
        // M = flex ? (v0sq*v1 - c1*v0) : v1 ;  n = bl * rsqrt(M·M) * M
        #pragma unroll
        for (int f = 0; f < 5; ++f) {
            float gx = wx, gy = wy, gz = wz;                // T_abs[0] = wrist
            float px = sm[base + 3*PALM5[f] + 0];
            float py = sm[base + 3*PALM5[f] + 1];
            float pz = sm[base + 3*PALM5[f] + 2];
            #pragma unroll
            for (int k = 0; k < 3; ++k) {
                const int i = 3 * f + k;
                const int ch = CH[i];
                const float bl =
                    (i < NBS) ? sblen[bbase + i] :
                    (i == 11) ? blr11 : (i == 12) ? blr12 :
                    (i == 13) ? blr13 : blr14;

                float v1x = sm[base + 3*ch + 0] - px;
                float v1y = sm[base + 3*ch + 1] - py;
                float v1z = sm[base + 3*ch + 2] - pz;
                float v0x = px - gx, v0y = py - gy, v0z = pz - gz;

                float c1   = v0x*v1x + v0y*v1y + v0z*v1z;
                float v0sq = v0x*v0x + v0y*v0y + v0z*v0z;

                bool flex = (c1 < 0.0f);
                float sA = flex ? v0sq : 1.0f;   // scale on v1
                float sB = flex ? c1   : 0.0f;   // scale on v0

                float mx = sA * v1x - sB * v0x;
                float my = sA * v1y - sB * v0y;
                float mz = sA * v1z - sB * v0z;
                float m2 = mx*mx + my*my + mz*mz;
                float w  = bl * rsqrtf(m2 + 1e-30f);

                float cx = px + w * mx;
                float cy = py + w * my;
                float cz = pz + w * mz;

                // child's raw joint value is dead now -> write output in place
                sm[base + 3*ch + 0] = cx;
                sm[base + 3*ch + 1] = cy;
                sm[base + 3*ch + 2] = cz;

                gx = px; gy = py; gz = pz;
                px = cx; py = cy; pz = cz;
            }
        }
    }
    __syncwarp();

    // ================= coalesced float4 store (own warp region) ================
    if (wfull) {
        #pragma unroll
        for (int i = 0; i < 16; ++i) {
            int q = i * 32 + lane;
            if (q < WV4)
                reinterpret_cast<float4*>(out + wg)[q] =
                    reinterpret_cast<const float4*>(sm + wsm)[q];
        }
    } else {
        for (int q = lane; q < WROW; q += 32) {
            long long g = wg + q;
            if (g < total) out[g] = sm[wsm + q];
        }
    }
}

extern "C" void kernel_launch(void* const* d_in, const int* in_sizes, int n_in,
                              void* d_out, int out_size)
{
    const float* joints = (const float*)d_in[0];
    const float* tempJ  = (const float*)d_in[1];
    float* out = (float*)d_out;
    const int n = in_sizes[0] / ROW;     // 131072
    const int blocks = (n + TPB - 1) / TPB;
    kin_kernel<<<blocks, TPB>>>(joints, tempJ, out, n);
}

// round 17
// speedup vs baseline: 1.0218x; 1.0218x over previous
#include <cuda_runtime.h>

#define TPB 128
#define ROW 63            // 21 joints * 3
#define WROW (32*ROW)     // 2016 floats per warp region
#define WV4 (WROW/4)      // 504 float4 per warp region
#define NSWEEP 3          // Jacobi sweeps (2 measured FAIL at 2.8e-3; 3 gives 1.2e-5)

// fast sqrt via MUFU.RSQ (no Newton tail); eps keeps 0 -> 0
__device__ __forceinline__ float fsqrt_fast(float x) {
    return x * rsqrtf(x + 1e-30f);
}

__global__ void __launch_bounds__(TPB, 7)
kin_kernel(const float* __restrict__ joints,
           const float* __restrict__ tempJ,
           float* out, int n)
{
    __shared__ __align__(16) float sm[TPB * ROW];   // 32256 B, reused 3x; 7 CTAs/SM
    const int tid  = threadIdx.x;
    const int lane = tid & 31;
    const int wid  = tid >> 5;
    const long long total = (long long)n * ROW;
    // per-warp global base: this warp's 32 samples
    const long long wg = ((long long)blockIdx.x * TPB + wid * 32) * ROW;
    const bool wfull = (wg + WROW) <= total;
    const bool active = ((long long)blockIdx.x * TPB + tid) < n;
    const int wsm = wid * WROW;          // warp's smem region
    const int base = tid * ROW;          // == wsm + lane*ROW
    float* outw = out + wg;              // warp's out region (also blen scratch)

    const int PALM5[5] = {1, 4, 7, 10, 13};
    const int CH[15] = {2,3,17, 5,6,18, 8,9,20, 11,12,19, 14,15,16};
    const int PA[15] = {1,2,3, 4,5,6, 7,8,9, 10,11,12, 13,14,15};

    // ====== prefetch this warp's joints region into L2 (consumed in phase 2) ======
    if (wfull) {
        const char* bp = (const char*)(joints + wg);   // 8064 B = 63 x 128B lines
        asm volatile("prefetch.global.L2 [%0];" :: "l"(bp + lane * 128));
        if (lane < 31)
            asm volatile("prefetch.global.L2 [%0];" :: "l"(bp + (32 + lane) * 128));
    }

    // ================= stage tempJ (coalesced float4, own warp region) =========
    if (wfull) {
        #pragma unroll
        for (int i = 0; i < 16; ++i) {
            int q = i * 32 + lane;
            if (q < WV4)
                reinterpret_cast<float4*>(sm + wsm)[q] =
                    reinterpret_cast<const float4*>(tempJ + wg)[q];
        }
    } else {
        for (int q = lane; q < WROW; q += 32) {
            long long g = wg + q;
            if (g < total) sm[wsm + q] = tempJ[g];
        }
    }
    __syncwarp();

    // extract from template: centered palm points (regs); bone lengths ->
    // scratch in the warp's own out region (overwritten by final store later).
    //   wfull:  slot q = i*32 + lane  (coalesced, q < 480 < WROW)
    //   !wfull: slot q = lane*63 + i  (own row -> in-bounds for active threads)
    float sp[5][3];
    if (active) {
        const float t0x = sm[base + 0], t0y = sm[base + 1], t0z = sm[base + 2];
        #pragma unroll
        for (int p = 0; p < 5; ++p) {
            sp[p][0] = sm[base + 3 * PALM5[p] + 0] - t0x;
            sp[p][1] = sm[base + 3 * PALM5[p] + 1] - t0y;
            sp[p][2] = sm[base + 3 * PALM5[p] + 2] - t0z;
        }
        #pragma unroll
        for (int i = 0; i < 15; ++i) {
            float bx = sm[base + 3*CH[i] + 0] - sm[base + 3*PA[i] + 0];
            float by = sm[base + 3*CH[i] + 1] - sm[base + 3*PA[i] + 1];
            float bz = sm[base + 3*CH[i] + 2] - sm[base + 3*PA[i] + 2];
            float bl = fsqrt_fast(bx*bx + by*by + bz*bz);
            outw[wfull ? (i * 32 + lane) : (lane * ROW + i)] = bl;
        }
    }
    __syncwarp();

    // ================= stage joints (overwrite own warp region) ================
    if (wfull) {
        #pragma unroll
        for (int i = 0; i < 16; ++i) {
            int q = i * 32 + lane;
            if (q < WV4)
                reinterpret_cast<float4*>(sm + wsm)[q] =
                    reinterpret_cast<const float4*>(joints + wg)[q];
        }
    } else {
        for (int q = lane; q < WROW; q += 32) {
            long long g = wg + q;
            if (g < total) sm[wsm + q] = joints[g];
        }
    }
    __syncwarp();

    if (active) {
        const float wx = sm[base + 0], wy = sm[base + 1], wz = sm[base + 2];

        // ---- H = sum_palm src ⊗ dst ----
        float H[3][3] = {{0,0,0},{0,0,0},{0,0,0}};
        #pragma unroll
        for (int p = 0; p < 5; ++p) {
            float jx = sm[base + 3 * PALM5[p] + 0] - wx;
            float jy = sm[base + 3 * PALM5[p] + 1] - wy;
            float jz = sm[base + 3 * PALM5[p] + 2] - wz;
            H[0][0] += sp[p][0]*jx; H[0][1] += sp[p][0]*jy; H[0][2] += sp[p][0]*jz;
            H[1][0] += sp[p][1]*jx; H[1][1] += sp[p][1]*jy; H[1][2] += sp[p][1]*jz;
            H[2][0] += sp[p][2]*jx; H[2][1] += sp[p][2]*jy; H[2][2] += sp[p][2]*jz;
        }

        // ---- A = H^T H ; NSWEEP-sweep division-free cyclic Jacobi ----
        float A[3][3];
        #pragma unroll
        for (int a = 0; a < 3; ++a)
            #pragma unroll
            for (int b = 0; b < 3; ++b)
                A[a][b] = H[0][a]*H[0][b] + H[1][a]*H[1][b] + H[2][a]*H[2][b];

        float V[3][3] = {{1,0,0},{0,1,0},{0,0,1}};
        #pragma unroll
        for (int sweep = 0; sweep < NSWEEP; ++sweep) {
            #pragma unroll
            for (int pair = 0; pair < 3; ++pair) {
                const int p = (pair == 2) ? 1 : 0;
                const int q = (pair == 0) ? 1 : 2;
                const int r = 3 - p - q;
                float apq = A[p][q];
                float x = 0.5f * (A[q][q] - A[p][p]);
                // inner rotation annihilating apq: tan(2θ) = apq/x, |θ| <= 45°
                float rinv = rsqrtf(x*x + apq*apq + 1e-36f);
                float co = (fabsf(x) + 1e-18f) * rinv;        // cos2θ (>=0)
                float si = apq * copysignf(1.0f, x) * rinv;   // sin2θ = apq·sign(x)/r
                float h  = 0.5f + 0.5f * co;                  // c²
                float cinv = rsqrtf(h);                       // 1/c
                float c = h * cinv;
                float s = 0.5f * si * cinv;
                float t = s * cinv;                           // tanθ
                A[p][p] -= t * apq;
                A[q][q] += t * apq;
                // after the very last rotation only the diagonal is consumed
                if (!(sweep == NSWEEP - 1 && pair == 2)) {
                    A[p][q] = 0.f; A[q][p] = 0.f;
                    float arp = A[r][p], arq = A[r][q];
                    A[r][p] = c * arp - s * arq; A[p][r] = A[r][p];
                    A[r][q] = s * arp + c * arq; A[q][r] = A[r][q];
                }
                #pragma unroll
                for (int k = 0; k < 3; ++k) {
                    float vp = V[k][p], vq = V[k][q];
                    V[k][p] = c * vp - s * vq;
                    V[k][q] = s * vp + c * vq;
                }
            }
        }

        // sort eigenvalues (descending) -> v1, v2; v3 = v1 x v2
        float e0 = A[0][0], e1 = A[1][1], e2 = A[2][2];
        int i0 = 0; float em = e0;
        if (e1 > em) { i0 = 1; em = e1; }
        if (e2 > em) { i0 = 2; em = e2; }
        const int a1 = (i0 + 1) % 3, b1 = (i0 + 2) % 3;
        float ea = (a1 == 0) ? e0 : (a1 == 1) ? e1 : e2;
        float eb = (b1 == 0) ? e0 : (b1 == 1) ? e1 : e2;
        const int i1 = (ea >= eb) ? a1 : b1;

        float v1[3], v2[3], v3[3];
        #pragma unroll
        for (int k = 0; k < 3; ++k) {
            v1[k] = (i0 == 0) ? V[k][0] : (i0 == 1) ? V[k][1] : V[k][2];
            v2[k] = (i1 == 0) ? V[k][0] : (i1 == 1) ? V[k][1] : V[k][2];
        }
        v3[0] = v1[1]*v2[2] - v1[2]*v2[1];
        v3[1] = v1[2]*v2[0] - v1[0]*v2[2];
        v3[2] = v1[0]*v2[1] - v1[1]*v2[0];

        // u1 = norm(H v1); u2 = norm(GS(H v2)); u3 = u1 x u2
        float u1[3], u2[3], u3[3];
        #pragma unroll
        for (int k = 0; k < 3; ++k)
            u1[k] = H[k][0]*v1[0] + H[k][1]*v1[1] + H[k][2]*v1[2];
        {
            float inv = rsqrtf(u1[0]*u1[0] + u1[1]*u1[1] + u1[2]*u1[2] + 1e-30f);
            u1[0] *= inv; u1[1] *= inv; u1[2] *= inv;
        }
        #pragma unroll
        for (int k = 0; k < 3; ++k)
            u2[k] = H[k][0]*v2[0] + H[k][1]*v2[1] + H[k][2]*v2[2];
        {
            float pr = u1[0]*u2[0] + u1[1]*u2[1] + u1[2]*u2[2];
            u2[0] -= pr * u1[0]; u2[1] -= pr * u1[1]; u2[2] -= pr * u1[2];
            float inv = rsqrtf(u2[0]*u2[0] + u2[1]*u2[1] + u2[2]*u2[2] + 1e-30f);
            u2[0] *= inv; u2[1] *= inv; u2[2] *= inv;
        }
        u3[0] = u1[1]*u2[2] - u1[2]*u2[1];
        u3[1] = u1[2]*u2[0] - u1[0]*u2[2];
        u3[2] = u1[0]*u2[1] - u1[1]*u2[0];

        // R = v1 u1^T + v2 u2^T + v3 u3^T
        float R[3][3];
        #pragma unroll
        for (int a = 0; a < 3; ++a)
            #pragma unroll
            for (int b = 0; b < 3; ++b)
                R[a][b] = v1[a]*u1[b] + v2[a]*u2[b] + v3[a]*u3[b];

        // ---- rotate template palm points (absolute coords), write in place ----
        #pragma unroll
        for (int p = 0; p < 5; ++p) {
            float tx = R[0][0]*sp[p][0] + R[0][1]*sp[p][1] + R[0][2]*sp[p][2] + wx;
            float ty = R[1][0]*sp[p][0] + R[1][1]*sp[p][1] + R[1][2]*sp[p][2] + wy;
            float tz = R[2][0]*sp[p][0] + R[2][1]*sp[p][1] + R[2][2]*sp[p][2] + wz;
            sm[base + 3*PALM5[p] + 0] = tx;
            sm[base + 3*PALM5[p] + 1] = ty;
            sm[base + 3*PALM5[p] + 2] = tz;
        }
        // wrist slot already holds w

        // ---- kinematic chain, finger-major, absolute coords, direct-M clamp ----
        // M = flex ? (v0sq*v1 - c1*v0) : v1 ;  n = bl * rsqrt(M·M) * M
        // bl read back from out-region scratch (L2-hot, batched independent LDGs)
        #pragma unroll
        for (int f = 0; f < 5; ++f) {
            float gx = wx, gy = wy, gz = wz;                // T_abs[0] = wrist
            float px = sm[base + 3*PALM5[f] + 0];
            float py = sm[base + 3*PALM5[f] + 1];
            float pz = sm[base + 3*PALM5[f] + 2];
            #pragma unroll
            for (int k = 0; k < 3; ++k) {
                const int i = 3 * f + k;
                const int ch = CH[i];
                const float bl = outw[wfull ? (i * 32 + lane) : (lane * ROW + i)];

                float v1x = sm[base + 3*ch + 0] - px;
                float v1y = sm[base + 3*ch + 1] - py;
                float v1z = sm[base + 3*ch + 2] - pz;
                float v0x = px - gx, v0y = py - gy, v0z = pz - gz;

                float c1   = v0x*v1x + v0y*v1y + v0z*v1z;
                float v0sq = v0x*v0x + v0y*v0y + v0z*v0z;

                bool flex = (c1 < 0.0f);
                float sA = flex ? v0sq : 1.0f;   // scale on v1
                float sB = flex ? c1   : 0.0f;   // scale on v0

                float mx = sA * v1x - sB * v0x;
                float my = sA * v1y - sB * v0y;
                float mz = sA * v1z - sB * v0z;
                float m2 = mx*mx + my*my + mz*mz;
                float w  = bl * rsqrtf(m2 + 1e-30f);

                float cx = px + w * mx;
                float cy = py + w * my;
                float cz = pz + w * mz;

                // child's raw joint value is dead now -> write output in place
                sm[base + 3*ch + 0] = cx;
                sm[base + 3*ch + 1] = cy;
                sm[base + 3*ch + 2] = cz;

                gx = px; gy = py; gz = pz;
                px = cx; py = cy; pz = cz;
            }
        }
    }
    __syncwarp();

    // ================= coalesced float4 store (own warp region) ================
    // overwrites the blen scratch with final output
    if (wfull) {
        #pragma unroll
        for (int i = 0; i < 16; ++i) {
            int q = i * 32 + lane;
            if (q < WV4)
                reinterpret_cast<float4*>(outw)[q] =
                    reinterpret_cast<const float4*>(sm + wsm)[q];
        }
    } else {
        for (int q = lane; q < WROW; q += 32) {
            long long g = wg + q;
            if (g < total) out[g] = sm[wsm + q];
        }
    }
}

extern "C" void kernel_launch(void* const* d_in, const int* in_sizes, int n_in,
                              void* d_out, int out_size)
{
    const float* joints = (const float*)d_in[0];
    const float* tempJ  = (const float*)d_in[1];
    float* out = (float*)d_out;
    const int n = in_sizes[0] / ROW;     // 131072
    const int blocks = (n + TPB - 1) / TPB;
    kin_kernel<<<blocks, TPB>>>(joints, tempJ, out, n);
}